// round 10
// baseline (speedup 1.0000x reference)
#include <cuda_runtime.h>
#include <cuda_bf16.h>
#include <cstdint>

#define Bb 2
#define Ss 2048
#define Hh 1024
#define NHh 16
#define HDd 64
#define Mm (Bb*Ss)

// Scratch (static device globals -- no allocation)
__device__ float g_q[(size_t)Mm * Hh];
__device__ float g_k[(size_t)Mm * Hh];
__device__ float g_v[(size_t)Mm * Hh];
__device__ float g_o[(size_t)Mm * Hh];

// ===========================================================================
// Warp-MMA helpers (plain sm_80+ PTX -- legal under the compute_103 target)
// ===========================================================================
__device__ __forceinline__ void ldsm_x4(uint32_t addr, uint32_t* r) {
    asm volatile("ldmatrix.sync.aligned.m8n8.x4.shared.b16 {%0,%1,%2,%3}, [%4];"
        : "=r"(r[0]), "=r"(r[1]), "=r"(r[2]), "=r"(r[3]) : "r"(addr));
}
__device__ __forceinline__ void mma_bf16(float* d, const uint32_t* a,
                                         const uint32_t* b) {
    asm volatile(
        "mma.sync.aligned.m16n8k16.row.col.f32.bf16.bf16.f32 "
        "{%0,%1,%2,%3}, {%4,%5,%6,%7}, {%8,%9}, {%0,%1,%2,%3};"
        : "+f"(d[0]), "+f"(d[1]), "+f"(d[2]), "+f"(d[3])
        : "r"(a[0]), "r"(a[1]), "r"(a[2]), "r"(a[3]), "r"(b[0]), "r"(b[1]));
}
__device__ __forceinline__ uint32_t smem_u32(const void* p) {
    uint32_t a;
    asm("{ .reg .u64 t; cvta.to.shared.u64 t, %1; cvt.u32.u64 %0, t; }"
        : "=r"(a) : "l"(p));
    return a;
}
__device__ __forceinline__ void split2(float a, float b, uint32_t& hi, uint32_t& lo) {
    __nv_bfloat16 ha = __float2bfloat16(a);
    __nv_bfloat16 hb = __float2bfloat16(b);
    __nv_bfloat162 h = __halves2bfloat162(ha, hb);
    __nv_bfloat162 l = __halves2bfloat162(
        __float2bfloat16(a - __bfloat162float(ha)),
        __float2bfloat16(b - __bfloat162float(hb)));
    hi = *reinterpret_cast<uint32_t*>(&h);
    lo = *reinterpret_cast<uint32_t*>(&l);
}
#define STSV2(addr, x, y) \
    asm volatile("st.shared.v2.b32 [%0], {%1,%2};" :: "r"(addr), "r"(x), "r"(y) : "memory")

// ===========================================================================
// Tensor-core GEMM (unchanged from R4): C = A @ B^T, bf16 hi/lo 3-MMA split.
// ===========================================================================
#define KTOT 1024
#define KC 32
#define NCH (KTOT / KC)
#define SROW 40
#define MATE (128 * SROW)
#define STAGE_E (4 * MATE)
#define GEMM_DSMEM (2 * STAGE_E * 2)

__global__ __launch_bounds__(256, 1) void gemm_tc(
    const float* __restrict__ A,
    const float* __restrict__ B0, const float* __restrict__ B1,
    const float* __restrict__ B2,
    float* __restrict__ C0, float* __restrict__ C1, float* __restrict__ C2)
{
    extern __shared__ __nv_bfloat16 sh[];

    const float* Bm = (blockIdx.z == 0) ? B0 : ((blockIdx.z == 1) ? B1 : B2);
    float*       Cm = (blockIdx.z == 0) ? C0 : ((blockIdx.z == 1) ? C1 : C2);

    const int tid = threadIdx.x;
    const int wid = tid >> 5, lane = tid & 31;
    const int wm = wid & 3, wn = wid >> 2;
    const int bm = blockIdx.x * 128;
    const int bn = blockIdx.y * 128;

    const int r = tid >> 1;
    const int half = (tid & 1) * 16;
    const float* Ag = A  + (size_t)(bm + r) * KTOT + half;
    const float* Bg = Bm + (size_t)(bn + r) * KTOT + half;
    const uint32_t sbase = smem_u32(sh);
    const uint32_t stoff = (uint32_t)(r * SROW + half) * 2;

    float4 ar[4], br[4];
    float acc[2][8][4];
#pragma unroll
    for (int mi = 0; mi < 2; mi++)
#pragma unroll
        for (int j = 0; j < 8; j++)
#pragma unroll
            for (int t = 0; t < 4; t++) acc[mi][j][t] = 0.f;

    const int la15 = lane & 15;
    const int a_koff = ((lane >> 4) & 1) * 8;
    const int b_n = (lane & 7) + ((lane & 16) ? 8 : 0);
    const int b_koff = (lane & 8) ? 8 : 0;

#pragma unroll
    for (int i = 0; i < 4; i++) {
        ar[i] = ((const float4*)Ag)[i];
        br[i] = ((const float4*)Bg)[i];
    }
    {
        const uint32_t st = sbase;
#pragma unroll
        for (int i = 0; i < 4; i++) {
            uint32_t h0, h1, l0, l1;
            split2(ar[i].x, ar[i].y, h0, l0);
            split2(ar[i].z, ar[i].w, h1, l1);
            STSV2(st + stoff + i * 8, h0, h1);
            STSV2(st + MATE * 2 + stoff + i * 8, l0, l1);
            split2(br[i].x, br[i].y, h0, l0);
            split2(br[i].z, br[i].w, h1, l1);
            STSV2(st + 2 * MATE * 2 + stoff + i * 8, h0, h1);
            STSV2(st + 3 * MATE * 2 + stoff + i * 8, l0, l1);
        }
    }
    __syncthreads();

    for (int c = 0; c < NCH; c++) {
        if (c + 1 < NCH) {
            const float* ap = Ag + (c + 1) * KC;
            const float* bp = Bg + (c + 1) * KC;
#pragma unroll
            for (int i = 0; i < 4; i++) {
                ar[i] = ((const float4*)ap)[i];
                br[i] = ((const float4*)bp)[i];
            }
        }
        {
            const uint32_t st = sbase + (uint32_t)(c & 1) * STAGE_E * 2;
#pragma unroll
            for (int ks = 0; ks < 2; ks++) {
                uint32_t ahi[2][4], alo[2][4];
                const uint32_t aaddr =
                    st + (uint32_t)((wm * 32 + la15) * SROW + ks * 16 + a_koff) * 2;
                ldsm_x4(aaddr,                 ahi[0]);
                ldsm_x4(aaddr + 16 * SROW * 2, ahi[1]);
                ldsm_x4(aaddr + MATE * 2,                 alo[0]);
                ldsm_x4(aaddr + MATE * 2 + 16 * SROW * 2, alo[1]);

                uint32_t bhi[16], blo[16];
                const uint32_t baddr = st + 2 * MATE * 2 +
                    (uint32_t)((wn * 64 + b_n) * SROW + ks * 16 + b_koff) * 2;
#pragma unroll
                for (int p = 0; p < 4; p++) {
                    ldsm_x4(baddr + p * 16 * SROW * 2,            &bhi[4 * p]);
                    ldsm_x4(baddr + MATE * 2 + p * 16 * SROW * 2, &blo[4 * p]);
                }
#pragma unroll
                for (int mi = 0; mi < 2; mi++)
#pragma unroll
                    for (int j = 0; j < 8; j++) {
                        mma_bf16(acc[mi][j], ahi[mi], &bhi[2 * j]);
                        mma_bf16(acc[mi][j], ahi[mi], &blo[2 * j]);
                        mma_bf16(acc[mi][j], alo[mi], &bhi[2 * j]);
                    }
            }
        }
        if (c + 1 < NCH) {
            const uint32_t st = sbase + (uint32_t)((c + 1) & 1) * STAGE_E * 2;
#pragma unroll
            for (int i = 0; i < 4; i++) {
                uint32_t h0, h1, l0, l1;
                split2(ar[i].x, ar[i].y, h0, l0);
                split2(ar[i].z, ar[i].w, h1, l1);
                STSV2(st + stoff + i * 8, h0, h1);
                STSV2(st + MATE * 2 + stoff + i * 8, l0, l1);
                split2(br[i].x, br[i].y, h0, l0);
                split2(br[i].z, br[i].w, h1, l1);
                STSV2(st + 2 * MATE * 2 + stoff + i * 8, h0, h1);
                STSV2(st + 3 * MATE * 2 + stoff + i * 8, l0, l1);
            }
        }
        __syncthreads();
    }
    {
        const int gr = lane >> 2;
        const int gc = (lane & 3) * 2;
#pragma unroll
        for (int mi = 0; mi < 2; mi++) {
            const int m0 = bm + wm * 32 + mi * 16 + gr;
#pragma unroll
            for (int j = 0; j < 8; j++) {
                const int n0 = bn + wn * 64 + j * 8 + gc;
                *(float2*)(Cm + (size_t)m0 * KTOT + n0) =
                    make_float2(acc[mi][j][0], acc[mi][j][1]);
                *(float2*)(Cm + (size_t)(m0 + 8) * KTOT + n0) =
                    make_float2(acc[mi][j][2], acc[mi][j][3]);
            }
        }
    }
}

// ---------------------------------------------------------------------------
// RoPE (interleaved pairs), bug-faithful (K rotation built from Q).
// ---------------------------------------------------------------------------
__global__ void rope_kernel(const float* __restrict__ fc,
                            const float* __restrict__ fs,
                            const int* __restrict__ pos)
{
    int idx = blockIdx.x * blockDim.x + threadIdx.x;
    if (idx >= Mm * (Hh / 2)) return;
    int pr = idx & 511;
    int ms = idx >> 9;
    int s  = ms & (Ss - 1);
    int d2 = pr & 31;
    int p  = pos[s];

    float c0 = fc[p * HDd + 2 * d2];
    float c1 = fc[p * HDd + 2 * d2 + 1];
    float s0 = fs[p * HDd + 2 * d2];
    float s1 = fs[p * HDd + 2 * d2 + 1];

    size_t base = (size_t)ms * Hh + pr * 2;
    float q0 = g_q[base], q1 = g_q[base + 1];
    float k0 = g_k[base], k1 = g_k[base + 1];

    g_q[base]     = q0 * c0 - q1 * s0;
    g_q[base + 1] = q1 * c1 + q0 * s1;
    g_k[base]     = k0 * c0 - q1 * s0;
    g_k[base + 1] = k1 * c1 + q0 * s1;
}

// ===========================================================================
// Causal flash attention, fp32, 128q x 128k tiles, 8x8 register score tiles.
// Q/K/V natural [row][64] with XOR-d4 swizzle; P swizzled along q4.
// ===========================================================================
// word offset of float4 (row, d4) in a swizzled [128][64] tile:
#define ASW(row, d4) ((row) * 64 + ((((d4) ^ (((row) >> 3) & 7))) << 2))
// P column swizzle: g depends on full row so exp-store lanes spread banks
#define PG(row) ((((row) & 7) ^ (((row) >> 3) & 7)))

#define QS_OFF 0
#define KS_OFF 8192
#define VS_OFF 16384
#define PT_OFF 24576          // [128][132]
#define MR_OFF 41472
#define LR_OFF 41600
#define AR_OFF 41728
#define RED_OFF 41856         // [16][132]
#define ATTN_FLOATS (RED_OFF + 16 * 132)
#define ATTN_SMEM (ATTN_FLOATS * 4)

__global__ __launch_bounds__(256, 1) void attn_kernel()
{
    extern __shared__ float sm[];
    float* Qs = sm + QS_OFF;
    float* Ks = sm + KS_OFF;
    float* Vs = sm + VS_OFF;
    float* Pt = sm + PT_OFF;
    float* mrow = sm + MR_OFF;
    float* lrow = sm + LR_OFF;
    float* arow = sm + AR_OFF;
    float* red  = sm + RED_OFF;

    const int qt = gridDim.x - 1 - blockIdx.x;   // long diagonals launch first
    const int bh = blockIdx.y;
    const int b = bh >> 4, h = bh & 15;
    const int tid = threadIdx.x;
    const int q0 = qt * 128;
    const int bS = b * Ss;
    const size_t hoff = (size_t)h * HDd;

    // ---- load Q tile (natural layout, swizzled, pre-scaled by 1/8) ----
#pragma unroll
    for (int it = 0; it < 8; it++) {
        int idx = it * 1024 + tid * 4;
        int qi = idx >> 6, d = idx & 63;
        float4 v = *(const float4*)&g_q[(size_t)(bS + q0 + qi) * Hh + hoff + d];
        v.x *= 0.125f; v.y *= 0.125f; v.z *= 0.125f; v.w *= 0.125f;
        *(float4*)&Qs[ASW(qi, d >> 2)] = v;
    }
    if (tid < 128) { mrow[tid] = -1e30f; lrow[tid] = 0.f; }

    float acc[8][4];
#pragma unroll
    for (int a = 0; a < 8; a++)
#pragma unroll
        for (int c = 0; c < 4; c++) acc[a][c] = 0.f;

    const int tq = tid & 15, tk = tid >> 4;
    const int tq8 = tq * 8, tk8 = tk * 8;
    const int tyq = tk;          // PV: q group (8 rows)
    const int txd = tq;          // PV: d4 group (4 cols)

    for (int kt = 0; kt <= qt; kt++) {
        __syncthreads();   // prev tile fully consumed
        const int k0g = kt * 128;
#pragma unroll
        for (int it = 0; it < 8; it++) {
            int idx = it * 1024 + tid * 4;
            int ki = idx >> 6, d = idx & 63;
            size_t gidx = (size_t)(bS + k0g + ki) * Hh + hoff + d;
            *(float4*)&Ks[ASW(ki, d >> 2)] = *(const float4*)&g_k[gidx];
            *(float4*)&Vs[ASW(ki, d >> 2)] = *(const float4*)&g_v[gidx];
        }
        __syncthreads();

        // ---- scores: sc[a][c] = K[tk8+a] . Q[tq8+c] ----
        float sc[8][8];
#pragma unroll
        for (int a = 0; a < 8; a++)
#pragma unroll
            for (int c = 0; c < 8; c++) sc[a][c] = 0.f;

#pragma unroll 4
        for (int d4 = 0; d4 < 16; d4++) {
            float4 qa[8];
#pragma unroll
            for (int c = 0; c < 8; c++)
                qa[c] = *(const float4*)&Qs[ASW(tq8 + c, d4)];
#pragma unroll
            for (int a = 0; a < 8; a++) {
                float4 ka = *(const float4*)&Ks[ASW(tk8 + a, d4)];
#pragma unroll
                for (int c = 0; c < 8; c++) {
                    sc[a][c] += ka.x * qa[c].x;
                    sc[a][c] += ka.y * qa[c].y;
                    sc[a][c] += ka.z * qa[c].z;
                    sc[a][c] += ka.w * qa[c].w;
                }
            }
        }

        if (kt == qt) {   // diagonal: causal mask
#pragma unroll
            for (int a = 0; a < 8; a++)
#pragma unroll
                for (int c = 0; c < 8; c++)
                    if (k0g + tk8 + a > q0 + tq8 + c) sc[a][c] = -1e30f;
        }

        // ---- partial max over this thread's 8 k, per q ----
        {
            float pm[8];
#pragma unroll
            for (int c = 0; c < 8; c++) {
                float m = sc[0][c];
#pragma unroll
                for (int a = 1; a < 8; a++) m = fmaxf(m, sc[a][c]);
                pm[c] = m;
            }
            *(float4*)&red[tk * 132 + tq8]     = make_float4(pm[0], pm[1], pm[2], pm[3]);
            *(float4*)&red[tk * 132 + tq8 + 4] = make_float4(pm[4], pm[5], pm[6], pm[7]);
        }
        __syncthreads();
        if (tid < 128) {
            float mn = red[tid];
#pragma unroll
            for (int r2 = 1; r2 < 16; r2++) mn = fmaxf(mn, red[r2 * 132 + tid]);
            float mo = mrow[tid];
            float mx = fmaxf(mn, mo);
            float al = __expf(mo - mx);
            mrow[tid] = mx; arow[tid] = al; lrow[tid] *= al;
        }
        __syncthreads();

        // ---- exp, store P (swizzled), partial sums ----
        {
            float mq[8];
            float4 m0 = *(const float4*)&mrow[tq8];
            float4 m1 = *(const float4*)&mrow[tq8 + 4];
            mq[0] = m0.x; mq[1] = m0.y; mq[2] = m0.z; mq[3] = m0.w;
            mq[4] = m1.x; mq[5] = m1.y; mq[6] = m1.z; mq[7] = m1.w;
            float ps[8];
#pragma unroll
            for (int c = 0; c < 8; c++) ps[c] = 0.f;
#pragma unroll
            for (int a = 0; a < 8; a++) {
                const int row = tk8 + a;
                const int g = PG(row);
                float e[8];
#pragma unroll
                for (int c = 0; c < 8; c++) {
                    e[c] = __expf(sc[a][c] - mq[c]);
                    ps[c] += e[c];
                }
                *(float4*)&Pt[row * 132 + (((tq * 2) ^ g) << 2)] =
                    make_float4(e[0], e[1], e[2], e[3]);
                *(float4*)&Pt[row * 132 + (((tq * 2 + 1) ^ g) << 2)] =
                    make_float4(e[4], e[5], e[6], e[7]);
            }
            *(float4*)&red[tk * 132 + tq8]     = make_float4(ps[0], ps[1], ps[2], ps[3]);
            *(float4*)&red[tk * 132 + tq8 + 4] = make_float4(ps[4], ps[5], ps[6], ps[7]);
        }
        __syncthreads();
        if (tid < 128) {
            float s = red[tid];
#pragma unroll
            for (int r2 = 1; r2 < 16; r2++) s += red[r2 * 132 + tid];
            lrow[tid] += s;
        }

        // ---- PV accumulate (reads arow/Pt/Vs; safe until next loop-top sync)
        {
            float al[8];
            float4 a0 = *(const float4*)&arow[tyq * 8];
            float4 a1 = *(const float4*)&arow[tyq * 8 + 4];
            al[0] = a0.x; al[1] = a0.y; al[2] = a0.z; al[3] = a0.w;
            al[4] = a1.x; al[5] = a1.y; al[6] = a1.z; al[7] = a1.w;
#pragma unroll
            for (int a = 0; a < 8; a++)
#pragma unroll
                for (int c = 0; c < 4; c++) acc[a][c] *= al[a];
#pragma unroll 4
            for (int k = 0; k < 128; k++) {
                const int gk = PG(k);
                float4 p0 = *(const float4*)&Pt[k * 132 + (((tyq * 2) ^ gk) << 2)];
                float4 p1 = *(const float4*)&Pt[k * 132 + (((tyq * 2 + 1) ^ gk) << 2)];
                float4 v  = *(const float4*)&Vs[ASW(k, txd)];
                acc[0][0] += p0.x * v.x; acc[0][1] += p0.x * v.y;
                acc[0][2] += p0.x * v.z; acc[0][3] += p0.x * v.w;
                acc[1][0] += p0.y * v.x; acc[1][1] += p0.y * v.y;
                acc[1][2] += p0.y * v.z; acc[1][3] += p0.y * v.w;
                acc[2][0] += p0.z * v.x; acc[2][1] += p0.z * v.y;
                acc[2][2] += p0.z * v.z; acc[2][3] += p0.z * v.w;
                acc[3][0] += p0.w * v.x; acc[3][1] += p0.w * v.y;
                acc[3][2] += p0.w * v.z; acc[3][3] += p0.w * v.w;
                acc[4][0] += p1.x * v.x; acc[4][1] += p1.x * v.y;
                acc[4][2] += p1.x * v.z; acc[4][3] += p1.x * v.w;
                acc[5][0] += p1.y * v.x; acc[5][1] += p1.y * v.y;
                acc[5][2] += p1.y * v.z; acc[5][3] += p1.y * v.w;
                acc[6][0] += p1.z * v.x; acc[6][1] += p1.z * v.y;
                acc[6][2] += p1.z * v.z; acc[6][3] += p1.z * v.w;
                acc[7][0] += p1.w * v.x; acc[7][1] += p1.w * v.y;
                acc[7][2] += p1.w * v.z; acc[7][3] += p1.w * v.w;
            }
        }
    }
    __syncthreads();

    // ---- normalize + write out [b, s, h, d] ----
    {
        float il[8];
        float4 l0 = *(const float4*)&lrow[tyq * 8];
        float4 l1 = *(const float4*)&lrow[tyq * 8 + 4];
        il[0] = 1.f / l0.x; il[1] = 1.f / l0.y; il[2] = 1.f / l0.z; il[3] = 1.f / l0.w;
        il[4] = 1.f / l1.x; il[5] = 1.f / l1.y; il[6] = 1.f / l1.z; il[7] = 1.f / l1.w;
#pragma unroll
        for (int a = 0; a < 8; a++) {
            int gq = q0 + tyq * 8 + a;
            float4 o = make_float4(acc[a][0] * il[a], acc[a][1] * il[a],
                                   acc[a][2] * il[a], acc[a][3] * il[a]);
            *(float4*)&g_o[(size_t)(bS + gq) * Hh + hoff + txd * 4] = o;
        }
    }
}

// ---------------------------------------------------------------------------

extern "C" void kernel_launch(void* const* d_in, const int* in_sizes, int n_in,
                              void* d_out, int out_size)
{
    const float* X   = (const float*)d_in[0];
    const float* fc  = (const float*)d_in[1];
    const float* fs  = (const float*)d_in[2];
    const int*   pos = (const int*)d_in[3];
    const float* Wq  = (const float*)d_in[4];
    const float* Wk  = (const float*)d_in[5];
    const float* Wv  = (const float*)d_in[6];
    const float* Wo  = (const float*)d_in[7];
    float* out = (float*)d_out;

    float *pq, *pk, *pv, *po;
    cudaGetSymbolAddress((void**)&pq, g_q);
    cudaGetSymbolAddress((void**)&pk, g_k);
    cudaGetSymbolAddress((void**)&pv, g_v);
    cudaGetSymbolAddress((void**)&po, g_o);

    cudaFuncSetAttribute(gemm_tc,
                         cudaFuncAttributeMaxDynamicSharedMemorySize, GEMM_DSMEM);
    cudaFuncSetAttribute(attn_kernel,
                         cudaFuncAttributeMaxDynamicSharedMemorySize, ATTN_SMEM);

    // 1) QKV projections (tensor cores)
    gemm_tc<<<dim3(Mm / 128, Hh / 128, 3), 256, GEMM_DSMEM>>>(
        X, Wq, Wk, Wv, pq, pk, pv);

    // 2) RoPE
    {
        int total = Mm * (Hh / 2);
        rope_kernel<<<(total + 255) / 256, 256>>>(fc, fs, pos);
    }

    // 3) Causal attention (fp32, 128x128 tiles)
    attn_kernel<<<dim3(Ss / 128, Bb * NHh), 256, ATTN_SMEM>>>();

    // 4) Output projection (tensor cores)
    gemm_tc<<<dim3(Mm / 128, Hh / 128, 1), 256, GEMM_DSMEM>>>(
        po, Wo, Wo, Wo, out, out, out);
}

// round 11
// speedup vs baseline: 1.0008x; 1.0008x over previous
#include <cuda_runtime.h>
#include <cuda_bf16.h>
#include <cstdint>

#define Bb 2
#define Ss 2048
#define Hh 1024
#define NHh 16
#define HDd 64
#define Mm (Bb*Ss)

// Scratch (static device globals -- no allocation)
__device__ float g_q[(size_t)Mm * Hh];
__device__ float g_k[(size_t)Mm * Hh];
__device__ float g_v[(size_t)Mm * Hh];
__device__ float g_o[(size_t)Mm * Hh];

// ===========================================================================
// Warp-MMA helpers (plain sm_80+ PTX -- legal under the compute_103 target)
// ===========================================================================
__device__ __forceinline__ void ldsm_x4(uint32_t addr, uint32_t* r) {
    asm volatile("ldmatrix.sync.aligned.m8n8.x4.shared.b16 {%0,%1,%2,%3}, [%4];"
        : "=r"(r[0]), "=r"(r[1]), "=r"(r[2]), "=r"(r[3]) : "r"(addr));
}
__device__ __forceinline__ void mma_bf16(float* d, const uint32_t* a,
                                         const uint32_t* b) {
    asm volatile(
        "mma.sync.aligned.m16n8k16.row.col.f32.bf16.bf16.f32 "
        "{%0,%1,%2,%3}, {%4,%5,%6,%7}, {%8,%9}, {%0,%1,%2,%3};"
        : "+f"(d[0]), "+f"(d[1]), "+f"(d[2]), "+f"(d[3])
        : "r"(a[0]), "r"(a[1]), "r"(a[2]), "r"(a[3]), "r"(b[0]), "r"(b[1]));
}
__device__ __forceinline__ uint32_t smem_u32(const void* p) {
    uint32_t a;
    asm("{ .reg .u64 t; cvta.to.shared.u64 t, %1; cvt.u32.u64 %0, t; }"
        : "=r"(a) : "l"(p));
    return a;
}
__device__ __forceinline__ void split2(float a, float b, uint32_t& hi, uint32_t& lo) {
    __nv_bfloat16 ha = __float2bfloat16(a);
    __nv_bfloat16 hb = __float2bfloat16(b);
    __nv_bfloat162 h = __halves2bfloat162(ha, hb);
    __nv_bfloat162 l = __halves2bfloat162(
        __float2bfloat16(a - __bfloat162float(ha)),
        __float2bfloat16(b - __bfloat162float(hb)));
    hi = *reinterpret_cast<uint32_t*>(&h);
    lo = *reinterpret_cast<uint32_t*>(&l);
}
#define STSV2(addr, x, y) \
    asm volatile("st.shared.v2.b32 [%0], {%1,%2};" :: "r"(addr), "r"(x), "r"(y) : "memory")

// ===========================================================================
// Tensor-core GEMM (unchanged from R4): C = A @ B^T, bf16 hi/lo 3-MMA split.
// ===========================================================================
#define KTOT 1024
#define KC 32
#define NCH (KTOT / KC)
#define SROW 40
#define MATE (128 * SROW)
#define STAGE_E (4 * MATE)
#define GEMM_DSMEM (2 * STAGE_E * 2)

__global__ __launch_bounds__(256, 1) void gemm_tc(
    const float* __restrict__ A,
    const float* __restrict__ B0, const float* __restrict__ B1,
    const float* __restrict__ B2,
    float* __restrict__ C0, float* __restrict__ C1, float* __restrict__ C2)
{
    extern __shared__ __nv_bfloat16 sh[];

    const float* Bm = (blockIdx.z == 0) ? B0 : ((blockIdx.z == 1) ? B1 : B2);
    float*       Cm = (blockIdx.z == 0) ? C0 : ((blockIdx.z == 1) ? C1 : C2);

    const int tid = threadIdx.x;
    const int wid = tid >> 5, lane = tid & 31;
    const int wm = wid & 3, wn = wid >> 2;
    const int bm = blockIdx.x * 128;
    const int bn = blockIdx.y * 128;

    const int r = tid >> 1;
    const int half = (tid & 1) * 16;
    const float* Ag = A  + (size_t)(bm + r) * KTOT + half;
    const float* Bg = Bm + (size_t)(bn + r) * KTOT + half;
    const uint32_t sbase = smem_u32(sh);
    const uint32_t stoff = (uint32_t)(r * SROW + half) * 2;

    float4 ar[4], br[4];
    float acc[2][8][4];
#pragma unroll
    for (int mi = 0; mi < 2; mi++)
#pragma unroll
        for (int j = 0; j < 8; j++)
#pragma unroll
            for (int t = 0; t < 4; t++) acc[mi][j][t] = 0.f;

    const int la15 = lane & 15;
    const int a_koff = ((lane >> 4) & 1) * 8;
    const int b_n = (lane & 7) + ((lane & 16) ? 8 : 0);
    const int b_koff = (lane & 8) ? 8 : 0;

#pragma unroll
    for (int i = 0; i < 4; i++) {
        ar[i] = ((const float4*)Ag)[i];
        br[i] = ((const float4*)Bg)[i];
    }
    {
        const uint32_t st = sbase;
#pragma unroll
        for (int i = 0; i < 4; i++) {
            uint32_t h0, h1, l0, l1;
            split2(ar[i].x, ar[i].y, h0, l0);
            split2(ar[i].z, ar[i].w, h1, l1);
            STSV2(st + stoff + i * 8, h0, h1);
            STSV2(st + MATE * 2 + stoff + i * 8, l0, l1);
            split2(br[i].x, br[i].y, h0, l0);
            split2(br[i].z, br[i].w, h1, l1);
            STSV2(st + 2 * MATE * 2 + stoff + i * 8, h0, h1);
            STSV2(st + 3 * MATE * 2 + stoff + i * 8, l0, l1);
        }
    }
    __syncthreads();

    for (int c = 0; c < NCH; c++) {
        if (c + 1 < NCH) {
            const float* ap = Ag + (c + 1) * KC;
            const float* bp = Bg + (c + 1) * KC;
#pragma unroll
            for (int i = 0; i < 4; i++) {
                ar[i] = ((const float4*)ap)[i];
                br[i] = ((const float4*)bp)[i];
            }
        }
        {
            const uint32_t st = sbase + (uint32_t)(c & 1) * STAGE_E * 2;
#pragma unroll
            for (int ks = 0; ks < 2; ks++) {
                uint32_t ahi[2][4], alo[2][4];
                const uint32_t aaddr =
                    st + (uint32_t)((wm * 32 + la15) * SROW + ks * 16 + a_koff) * 2;
                ldsm_x4(aaddr,                 ahi[0]);
                ldsm_x4(aaddr + 16 * SROW * 2, ahi[1]);
                ldsm_x4(aaddr + MATE * 2,                 alo[0]);
                ldsm_x4(aaddr + MATE * 2 + 16 * SROW * 2, alo[1]);

                uint32_t bhi[16], blo[16];
                const uint32_t baddr = st + 2 * MATE * 2 +
                    (uint32_t)((wn * 64 + b_n) * SROW + ks * 16 + b_koff) * 2;
#pragma unroll
                for (int p = 0; p < 4; p++) {
                    ldsm_x4(baddr + p * 16 * SROW * 2,            &bhi[4 * p]);
                    ldsm_x4(baddr + MATE * 2 + p * 16 * SROW * 2, &blo[4 * p]);
                }
#pragma unroll
                for (int mi = 0; mi < 2; mi++)
#pragma unroll
                    for (int j = 0; j < 8; j++) {
                        mma_bf16(acc[mi][j], ahi[mi], &bhi[2 * j]);
                        mma_bf16(acc[mi][j], ahi[mi], &blo[2 * j]);
                        mma_bf16(acc[mi][j], alo[mi], &bhi[2 * j]);
                    }
            }
        }
        if (c + 1 < NCH) {
            const uint32_t st = sbase + (uint32_t)((c + 1) & 1) * STAGE_E * 2;
#pragma unroll
            for (int i = 0; i < 4; i++) {
                uint32_t h0, h1, l0, l1;
                split2(ar[i].x, ar[i].y, h0, l0);
                split2(ar[i].z, ar[i].w, h1, l1);
                STSV2(st + stoff + i * 8, h0, h1);
                STSV2(st + MATE * 2 + stoff + i * 8, l0, l1);
                split2(br[i].x, br[i].y, h0, l0);
                split2(br[i].z, br[i].w, h1, l1);
                STSV2(st + 2 * MATE * 2 + stoff + i * 8, h0, h1);
                STSV2(st + 3 * MATE * 2 + stoff + i * 8, l0, l1);
            }
        }
        __syncthreads();
    }
    {
        const int gr = lane >> 2;
        const int gc = (lane & 3) * 2;
#pragma unroll
        for (int mi = 0; mi < 2; mi++) {
            const int m0 = bm + wm * 32 + mi * 16 + gr;
#pragma unroll
            for (int j = 0; j < 8; j++) {
                const int n0 = bn + wn * 64 + j * 8 + gc;
                *(float2*)(Cm + (size_t)m0 * KTOT + n0) =
                    make_float2(acc[mi][j][0], acc[mi][j][1]);
                *(float2*)(Cm + (size_t)(m0 + 8) * KTOT + n0) =
                    make_float2(acc[mi][j][2], acc[mi][j][3]);
            }
        }
    }
}

// ---------------------------------------------------------------------------
// RoPE (interleaved pairs), bug-faithful (K rotation built from Q).
// ---------------------------------------------------------------------------
__global__ void rope_kernel(const float* __restrict__ fc,
                            const float* __restrict__ fs,
                            const int* __restrict__ pos)
{
    int idx = blockIdx.x * blockDim.x + threadIdx.x;
    if (idx >= Mm * (Hh / 2)) return;
    int pr = idx & 511;
    int ms = idx >> 9;
    int s  = ms & (Ss - 1);
    int d2 = pr & 31;
    int p  = pos[s];

    float c0 = fc[p * HDd + 2 * d2];
    float c1 = fc[p * HDd + 2 * d2 + 1];
    float s0 = fs[p * HDd + 2 * d2];
    float s1 = fs[p * HDd + 2 * d2 + 1];

    size_t base = (size_t)ms * Hh + pr * 2;
    float q0 = g_q[base], q1 = g_q[base + 1];
    float k0 = g_k[base], k1 = g_k[base + 1];

    g_q[base]     = q0 * c0 - q1 * s0;
    g_q[base + 1] = q1 * c1 + q0 * s1;
    g_k[base]     = k0 * c0 - q1 * s0;
    g_k[base + 1] = k1 * c1 + q0 * s1;
}

// ===========================================================================
// Causal flash attention, fp32, 128q x 128k tiles, 8x8 register score tiles.
// Q/K/V natural [row][64] with XOR-d4 swizzle; P swizzled along q4.
// ===========================================================================
// word offset of float4 (row, d4) in a swizzled [128][64] tile:
#define ASW(row, d4) ((row) * 64 + ((((d4) ^ (((row) >> 3) & 7))) << 2))
// P column swizzle: g depends on full row so exp-store lanes spread banks
#define PG(row) ((((row) & 7) ^ (((row) >> 3) & 7)))

#define QS_OFF 0
#define KS_OFF 8192
#define VS_OFF 16384
#define PT_OFF 24576          // [128][132]
#define MR_OFF 41472
#define LR_OFF 41600
#define AR_OFF 41728
#define RED_OFF 41856         // [16][132]
#define ATTN_FLOATS (RED_OFF + 16 * 132)
#define ATTN_SMEM (ATTN_FLOATS * 4)

__global__ __launch_bounds__(256, 1) void attn_kernel()
{
    extern __shared__ float sm[];
    float* Qs = sm + QS_OFF;
    float* Ks = sm + KS_OFF;
    float* Vs = sm + VS_OFF;
    float* Pt = sm + PT_OFF;
    float* mrow = sm + MR_OFF;
    float* lrow = sm + LR_OFF;
    float* arow = sm + AR_OFF;
    float* red  = sm + RED_OFF;

    const int qt = gridDim.x - 1 - blockIdx.x;   // long diagonals launch first
    const int bh = blockIdx.y;
    const int b = bh >> 4, h = bh & 15;
    const int tid = threadIdx.x;
    const int q0 = qt * 128;
    const int bS = b * Ss;
    const size_t hoff = (size_t)h * HDd;

    // ---- load Q tile (natural layout, swizzled, pre-scaled by 1/8) ----
#pragma unroll
    for (int it = 0; it < 8; it++) {
        int idx = it * 1024 + tid * 4;
        int qi = idx >> 6, d = idx & 63;
        float4 v = *(const float4*)&g_q[(size_t)(bS + q0 + qi) * Hh + hoff + d];
        v.x *= 0.125f; v.y *= 0.125f; v.z *= 0.125f; v.w *= 0.125f;
        *(float4*)&Qs[ASW(qi, d >> 2)] = v;
    }
    if (tid < 128) { mrow[tid] = -1e30f; lrow[tid] = 0.f; }

    float acc[8][4];
#pragma unroll
    for (int a = 0; a < 8; a++)
#pragma unroll
        for (int c = 0; c < 4; c++) acc[a][c] = 0.f;

    const int tq = tid & 15, tk = tid >> 4;
    const int tq8 = tq * 8, tk8 = tk * 8;
    const int tyq = tk;          // PV: q group (8 rows)
    const int txd = tq;          // PV: d4 group (4 cols)

    for (int kt = 0; kt <= qt; kt++) {
        __syncthreads();   // prev tile fully consumed
        const int k0g = kt * 128;
#pragma unroll
        for (int it = 0; it < 8; it++) {
            int idx = it * 1024 + tid * 4;
            int ki = idx >> 6, d = idx & 63;
            size_t gidx = (size_t)(bS + k0g + ki) * Hh + hoff + d;
            *(float4*)&Ks[ASW(ki, d >> 2)] = *(const float4*)&g_k[gidx];
            *(float4*)&Vs[ASW(ki, d >> 2)] = *(const float4*)&g_v[gidx];
        }
        __syncthreads();

        // ---- scores: sc[a][c] = K[tk8+a] . Q[tq8+c] ----
        float sc[8][8];
#pragma unroll
        for (int a = 0; a < 8; a++)
#pragma unroll
            for (int c = 0; c < 8; c++) sc[a][c] = 0.f;

#pragma unroll 4
        for (int d4 = 0; d4 < 16; d4++) {
            float4 qa[8];
#pragma unroll
            for (int c = 0; c < 8; c++)
                qa[c] = *(const float4*)&Qs[ASW(tq8 + c, d4)];
#pragma unroll
            for (int a = 0; a < 8; a++) {
                float4 ka = *(const float4*)&Ks[ASW(tk8 + a, d4)];
#pragma unroll
                for (int c = 0; c < 8; c++) {
                    sc[a][c] += ka.x * qa[c].x;
                    sc[a][c] += ka.y * qa[c].y;
                    sc[a][c] += ka.z * qa[c].z;
                    sc[a][c] += ka.w * qa[c].w;
                }
            }
        }

        if (kt == qt) {   // diagonal: causal mask
#pragma unroll
            for (int a = 0; a < 8; a++)
#pragma unroll
                for (int c = 0; c < 8; c++)
                    if (k0g + tk8 + a > q0 + tq8 + c) sc[a][c] = -1e30f;
        }

        // ---- partial max over this thread's 8 k, per q ----
        {
            float pm[8];
#pragma unroll
            for (int c = 0; c < 8; c++) {
                float m = sc[0][c];
#pragma unroll
                for (int a = 1; a < 8; a++) m = fmaxf(m, sc[a][c]);
                pm[c] = m;
            }
            *(float4*)&red[tk * 132 + tq8]     = make_float4(pm[0], pm[1], pm[2], pm[3]);
            *(float4*)&red[tk * 132 + tq8 + 4] = make_float4(pm[4], pm[5], pm[6], pm[7]);
        }
        __syncthreads();
        if (tid < 128) {
            float mn = red[tid];
#pragma unroll
            for (int r2 = 1; r2 < 16; r2++) mn = fmaxf(mn, red[r2 * 132 + tid]);
            float mo = mrow[tid];
            float mx = fmaxf(mn, mo);
            float al = __expf(mo - mx);
            mrow[tid] = mx; arow[tid] = al; lrow[tid] *= al;
        }
        __syncthreads();

        // ---- exp, store P (swizzled), partial sums ----
        {
            float mq[8];
            float4 m0 = *(const float4*)&mrow[tq8];
            float4 m1 = *(const float4*)&mrow[tq8 + 4];
            mq[0] = m0.x; mq[1] = m0.y; mq[2] = m0.z; mq[3] = m0.w;
            mq[4] = m1.x; mq[5] = m1.y; mq[6] = m1.z; mq[7] = m1.w;
            float ps[8];
#pragma unroll
            for (int c = 0; c < 8; c++) ps[c] = 0.f;
#pragma unroll
            for (int a = 0; a < 8; a++) {
                const int row = tk8 + a;
                const int g = PG(row);
                float e[8];
#pragma unroll
                for (int c = 0; c < 8; c++) {
                    e[c] = __expf(sc[a][c] - mq[c]);
                    ps[c] += e[c];
                }
                *(float4*)&Pt[row * 132 + (((tq * 2) ^ g) << 2)] =
                    make_float4(e[0], e[1], e[2], e[3]);
                *(float4*)&Pt[row * 132 + (((tq * 2 + 1) ^ g) << 2)] =
                    make_float4(e[4], e[5], e[6], e[7]);
            }
            *(float4*)&red[tk * 132 + tq8]     = make_float4(ps[0], ps[1], ps[2], ps[3]);
            *(float4*)&red[tk * 132 + tq8 + 4] = make_float4(ps[4], ps[5], ps[6], ps[7]);
        }
        __syncthreads();
        if (tid < 128) {
            float s = red[tid];
#pragma unroll
            for (int r2 = 1; r2 < 16; r2++) s += red[r2 * 132 + tid];
            lrow[tid] += s;
        }

        // ---- PV accumulate (reads arow/Pt/Vs; safe until next loop-top sync)
        {
            float al[8];
            float4 a0 = *(const float4*)&arow[tyq * 8];
            float4 a1 = *(const float4*)&arow[tyq * 8 + 4];
            al[0] = a0.x; al[1] = a0.y; al[2] = a0.z; al[3] = a0.w;
            al[4] = a1.x; al[5] = a1.y; al[6] = a1.z; al[7] = a1.w;
#pragma unroll
            for (int a = 0; a < 8; a++)
#pragma unroll
                for (int c = 0; c < 4; c++) acc[a][c] *= al[a];
#pragma unroll 4
            for (int k = 0; k < 128; k++) {
                const int gk = PG(k);
                float4 p0 = *(const float4*)&Pt[k * 132 + (((tyq * 2) ^ gk) << 2)];
                float4 p1 = *(const float4*)&Pt[k * 132 + (((tyq * 2 + 1) ^ gk) << 2)];
                float4 v  = *(const float4*)&Vs[ASW(k, txd)];
                acc[0][0] += p0.x * v.x; acc[0][1] += p0.x * v.y;
                acc[0][2] += p0.x * v.z; acc[0][3] += p0.x * v.w;
                acc[1][0] += p0.y * v.x; acc[1][1] += p0.y * v.y;
                acc[1][2] += p0.y * v.z; acc[1][3] += p0.y * v.w;
                acc[2][0] += p0.z * v.x; acc[2][1] += p0.z * v.y;
                acc[2][2] += p0.z * v.z; acc[2][3] += p0.z * v.w;
                acc[3][0] += p0.w * v.x; acc[3][1] += p0.w * v.y;
                acc[3][2] += p0.w * v.z; acc[3][3] += p0.w * v.w;
                acc[4][0] += p1.x * v.x; acc[4][1] += p1.x * v.y;
                acc[4][2] += p1.x * v.z; acc[4][3] += p1.x * v.w;
                acc[5][0] += p1.y * v.x; acc[5][1] += p1.y * v.y;
                acc[5][2] += p1.y * v.z; acc[5][3] += p1.y * v.w;
                acc[6][0] += p1.z * v.x; acc[6][1] += p1.z * v.y;
                acc[6][2] += p1.z * v.z; acc[6][3] += p1.z * v.w;
                acc[7][0] += p1.w * v.x; acc[7][1] += p1.w * v.y;
                acc[7][2] += p1.w * v.z; acc[7][3] += p1.w * v.w;
            }
        }
    }
    __syncthreads();

    // ---- normalize + write out [b, s, h, d] ----
    {
        float il[8];
        float4 l0 = *(const float4*)&lrow[tyq * 8];
        float4 l1 = *(const float4*)&lrow[tyq * 8 + 4];
        il[0] = 1.f / l0.x; il[1] = 1.f / l0.y; il[2] = 1.f / l0.z; il[3] = 1.f / l0.w;
        il[4] = 1.f / l1.x; il[5] = 1.f / l1.y; il[6] = 1.f / l1.z; il[7] = 1.f / l1.w;
#pragma unroll
        for (int a = 0; a < 8; a++) {
            int gq = q0 + tyq * 8 + a;
            float4 o = make_float4(acc[a][0] * il[a], acc[a][1] * il[a],
                                   acc[a][2] * il[a], acc[a][3] * il[a]);
            *(float4*)&g_o[(size_t)(bS + gq) * Hh + hoff + txd * 4] = o;
        }
    }
}

// ---------------------------------------------------------------------------

extern "C" void kernel_launch(void* const* d_in, const int* in_sizes, int n_in,
                              void* d_out, int out_size)
{
    const float* X   = (const float*)d_in[0];
    const float* fc  = (const float*)d_in[1];
    const float* fs  = (const float*)d_in[2];
    const int*   pos = (const int*)d_in[3];
    const float* Wq  = (const float*)d_in[4];
    const float* Wk  = (const float*)d_in[5];
    const float* Wv  = (const float*)d_in[6];
    const float* Wo  = (const float*)d_in[7];
    float* out = (float*)d_out;

    float *pq, *pk, *pv, *po;
    cudaGetSymbolAddress((void**)&pq, g_q);
    cudaGetSymbolAddress((void**)&pk, g_k);
    cudaGetSymbolAddress((void**)&pv, g_v);
    cudaGetSymbolAddress((void**)&po, g_o);

    cudaFuncSetAttribute(gemm_tc,
                         cudaFuncAttributeMaxDynamicSharedMemorySize, GEMM_DSMEM);
    cudaFuncSetAttribute(attn_kernel,
                         cudaFuncAttributeMaxDynamicSharedMemorySize, ATTN_SMEM);

    // 1) QKV projections (tensor cores)
    gemm_tc<<<dim3(Mm / 128, Hh / 128, 3), 256, GEMM_DSMEM>>>(
        X, Wq, Wk, Wv, pq, pk, pv);

    // 2) RoPE
    {
        int total = Mm * (Hh / 2);
        rope_kernel<<<(total + 255) / 256, 256>>>(fc, fs, pos);
    }

    // 3) Causal attention (fp32, 128x128 tiles)
    attn_kernel<<<dim3(Ss / 128, Bb * NHh), 256, ATTN_SMEM>>>();

    // 4) Output projection (tensor cores)
    gemm_tc<<<dim3(Mm / 128, Hh / 128, 1), 256, GEMM_DSMEM>>>(
        po, Wo, Wo, Wo, out, out, out);
}

// round 12
// speedup vs baseline: 1.0016x; 1.0008x over previous
#include <cuda_runtime.h>
#include <cuda_bf16.h>
#include <cstdint>

#define Bb 2
#define Ss 2048
#define Hh 1024
#define NHh 16
#define HDd 64
#define Mm (Bb*Ss)

// Scratch (static device globals -- no allocation)
__device__ float g_q[(size_t)Mm * Hh];
__device__ float g_k[(size_t)Mm * Hh];
__device__ float g_v[(size_t)Mm * Hh];
__device__ float g_o[(size_t)Mm * Hh];

// ===========================================================================
// Warp-MMA helpers (plain sm_80+ PTX -- legal under the compute_103 target)
// ===========================================================================
__device__ __forceinline__ void ldsm_x4(uint32_t addr, uint32_t* r) {
    asm volatile("ldmatrix.sync.aligned.m8n8.x4.shared.b16 {%0,%1,%2,%3}, [%4];"
        : "=r"(r[0]), "=r"(r[1]), "=r"(r[2]), "=r"(r[3]) : "r"(addr));
}
__device__ __forceinline__ void mma_bf16(float* d, const uint32_t* a,
                                         const uint32_t* b) {
    asm volatile(
        "mma.sync.aligned.m16n8k16.row.col.f32.bf16.bf16.f32 "
        "{%0,%1,%2,%3}, {%4,%5,%6,%7}, {%8,%9}, {%0,%1,%2,%3};"
        : "+f"(d[0]), "+f"(d[1]), "+f"(d[2]), "+f"(d[3])
        : "r"(a[0]), "r"(a[1]), "r"(a[2]), "r"(a[3]), "r"(b[0]), "r"(b[1]));
}
__device__ __forceinline__ uint32_t smem_u32(const void* p) {
    uint32_t a;
    asm("{ .reg .u64 t; cvta.to.shared.u64 t, %1; cvt.u32.u64 %0, t; }"
        : "=r"(a) : "l"(p));
    return a;
}
__device__ __forceinline__ void split2(float a, float b, uint32_t& hi, uint32_t& lo) {
    __nv_bfloat16 ha = __float2bfloat16(a);
    __nv_bfloat16 hb = __float2bfloat16(b);
    __nv_bfloat162 h = __halves2bfloat162(ha, hb);
    __nv_bfloat162 l = __halves2bfloat162(
        __float2bfloat16(a - __bfloat162float(ha)),
        __float2bfloat16(b - __bfloat162float(hb)));
    hi = *reinterpret_cast<uint32_t*>(&h);
    lo = *reinterpret_cast<uint32_t*>(&l);
}
#define STSV2(addr, x, y) \
    asm volatile("st.shared.v2.b32 [%0], {%1,%2};" :: "r"(addr), "r"(x), "r"(y) : "memory")

// ===========================================================================
// Tensor-core GEMM (unchanged from R4): C = A @ B^T, bf16 hi/lo 3-MMA split.
// ===========================================================================
#define KTOT 1024
#define KC 32
#define NCH (KTOT / KC)
#define SROW 40
#define MATE (128 * SROW)
#define STAGE_E (4 * MATE)
#define GEMM_DSMEM (2 * STAGE_E * 2)

__global__ __launch_bounds__(256, 1) void gemm_tc(
    const float* __restrict__ A,
    const float* __restrict__ B0, const float* __restrict__ B1,
    const float* __restrict__ B2,
    float* __restrict__ C0, float* __restrict__ C1, float* __restrict__ C2)
{
    extern __shared__ __nv_bfloat16 sh[];

    const float* Bm = (blockIdx.z == 0) ? B0 : ((blockIdx.z == 1) ? B1 : B2);
    float*       Cm = (blockIdx.z == 0) ? C0 : ((blockIdx.z == 1) ? C1 : C2);

    const int tid = threadIdx.x;
    const int wid = tid >> 5, lane = tid & 31;
    const int wm = wid & 3, wn = wid >> 2;
    const int bm = blockIdx.x * 128;
    const int bn = blockIdx.y * 128;

    const int r = tid >> 1;
    const int half = (tid & 1) * 16;
    const float* Ag = A  + (size_t)(bm + r) * KTOT + half;
    const float* Bg = Bm + (size_t)(bn + r) * KTOT + half;
    const uint32_t sbase = smem_u32(sh);
    const uint32_t stoff = (uint32_t)(r * SROW + half) * 2;

    float4 ar[4], br[4];
    float acc[2][8][4];
#pragma unroll
    for (int mi = 0; mi < 2; mi++)
#pragma unroll
        for (int j = 0; j < 8; j++)
#pragma unroll
            for (int t = 0; t < 4; t++) acc[mi][j][t] = 0.f;

    const int la15 = lane & 15;
    const int a_koff = ((lane >> 4) & 1) * 8;
    const int b_n = (lane & 7) + ((lane & 16) ? 8 : 0);
    const int b_koff = (lane & 8) ? 8 : 0;

#pragma unroll
    for (int i = 0; i < 4; i++) {
        ar[i] = ((const float4*)Ag)[i];
        br[i] = ((const float4*)Bg)[i];
    }
    {
        const uint32_t st = sbase;
#pragma unroll
        for (int i = 0; i < 4; i++) {
            uint32_t h0, h1, l0, l1;
            split2(ar[i].x, ar[i].y, h0, l0);
            split2(ar[i].z, ar[i].w, h1, l1);
            STSV2(st + stoff + i * 8, h0, h1);
            STSV2(st + MATE * 2 + stoff + i * 8, l0, l1);
            split2(br[i].x, br[i].y, h0, l0);
            split2(br[i].z, br[i].w, h1, l1);
            STSV2(st + 2 * MATE * 2 + stoff + i * 8, h0, h1);
            STSV2(st + 3 * MATE * 2 + stoff + i * 8, l0, l1);
        }
    }
    __syncthreads();

    for (int c = 0; c < NCH; c++) {
        if (c + 1 < NCH) {
            const float* ap = Ag + (c + 1) * KC;
            const float* bp = Bg + (c + 1) * KC;
#pragma unroll
            for (int i = 0; i < 4; i++) {
                ar[i] = ((const float4*)ap)[i];
                br[i] = ((const float4*)bp)[i];
            }
        }
        {
            const uint32_t st = sbase + (uint32_t)(c & 1) * STAGE_E * 2;
#pragma unroll
            for (int ks = 0; ks < 2; ks++) {
                uint32_t ahi[2][4], alo[2][4];
                const uint32_t aaddr =
                    st + (uint32_t)((wm * 32 + la15) * SROW + ks * 16 + a_koff) * 2;
                ldsm_x4(aaddr,                 ahi[0]);
                ldsm_x4(aaddr + 16 * SROW * 2, ahi[1]);
                ldsm_x4(aaddr + MATE * 2,                 alo[0]);
                ldsm_x4(aaddr + MATE * 2 + 16 * SROW * 2, alo[1]);

                uint32_t bhi[16], blo[16];
                const uint32_t baddr = st + 2 * MATE * 2 +
                    (uint32_t)((wn * 64 + b_n) * SROW + ks * 16 + b_koff) * 2;
#pragma unroll
                for (int p = 0; p < 4; p++) {
                    ldsm_x4(baddr + p * 16 * SROW * 2,            &bhi[4 * p]);
                    ldsm_x4(baddr + MATE * 2 + p * 16 * SROW * 2, &blo[4 * p]);
                }
#pragma unroll
                for (int mi = 0; mi < 2; mi++)
#pragma unroll
                    for (int j = 0; j < 8; j++) {
                        mma_bf16(acc[mi][j], ahi[mi], &bhi[2 * j]);
                        mma_bf16(acc[mi][j], ahi[mi], &blo[2 * j]);
                        mma_bf16(acc[mi][j], alo[mi], &bhi[2 * j]);
                    }
            }
        }
        if (c + 1 < NCH) {
            const uint32_t st = sbase + (uint32_t)((c + 1) & 1) * STAGE_E * 2;
#pragma unroll
            for (int i = 0; i < 4; i++) {
                uint32_t h0, h1, l0, l1;
                split2(ar[i].x, ar[i].y, h0, l0);
                split2(ar[i].z, ar[i].w, h1, l1);
                STSV2(st + stoff + i * 8, h0, h1);
                STSV2(st + MATE * 2 + stoff + i * 8, l0, l1);
                split2(br[i].x, br[i].y, h0, l0);
                split2(br[i].z, br[i].w, h1, l1);
                STSV2(st + 2 * MATE * 2 + stoff + i * 8, h0, h1);
                STSV2(st + 3 * MATE * 2 + stoff + i * 8, l0, l1);
            }
        }
        __syncthreads();
    }
    {
        const int gr = lane >> 2;
        const int gc = (lane & 3) * 2;
#pragma unroll
        for (int mi = 0; mi < 2; mi++) {
            const int m0 = bm + wm * 32 + mi * 16 + gr;
#pragma unroll
            for (int j = 0; j < 8; j++) {
                const int n0 = bn + wn * 64 + j * 8 + gc;
                *(float2*)(Cm + (size_t)m0 * KTOT + n0) =
                    make_float2(acc[mi][j][0], acc[mi][j][1]);
                *(float2*)(Cm + (size_t)(m0 + 8) * KTOT + n0) =
                    make_float2(acc[mi][j][2], acc[mi][j][3]);
            }
        }
    }
}

// ---------------------------------------------------------------------------
// RoPE (interleaved pairs), bug-faithful (K rotation built from Q).
// ---------------------------------------------------------------------------
__global__ void rope_kernel(const float* __restrict__ fc,
                            const float* __restrict__ fs,
                            const int* __restrict__ pos)
{
    int idx = blockIdx.x * blockDim.x + threadIdx.x;
    if (idx >= Mm * (Hh / 2)) return;
    int pr = idx & 511;
    int ms = idx >> 9;
    int s  = ms & (Ss - 1);
    int d2 = pr & 31;
    int p  = pos[s];

    float c0 = fc[p * HDd + 2 * d2];
    float c1 = fc[p * HDd + 2 * d2 + 1];
    float s0 = fs[p * HDd + 2 * d2];
    float s1 = fs[p * HDd + 2 * d2 + 1];

    size_t base = (size_t)ms * Hh + pr * 2;
    float q0 = g_q[base], q1 = g_q[base + 1];
    float k0 = g_k[base], k1 = g_k[base + 1];

    g_q[base]     = q0 * c0 - q1 * s0;
    g_q[base + 1] = q1 * c1 + q0 * s1;
    g_k[base]     = k0 * c0 - q1 * s0;
    g_k[base + 1] = k1 * c1 + q0 * s1;
}

// ===========================================================================
// Causal flash attention, fp32, 128q x 128k tiles, 8x8 register score tiles.
// Q/K/V natural [row][64] with XOR-d4 swizzle; P swizzled along q4.
// ===========================================================================
// word offset of float4 (row, d4) in a swizzled [128][64] tile:
#define ASW(row, d4) ((row) * 64 + ((((d4) ^ (((row) >> 3) & 7))) << 2))
// P column swizzle: g depends on full row so exp-store lanes spread banks
#define PG(row) ((((row) & 7) ^ (((row) >> 3) & 7)))

#define QS_OFF 0
#define KS_OFF 8192
#define VS_OFF 16384
#define PT_OFF 24576          // [128][132]
#define MR_OFF 41472
#define LR_OFF 41600
#define AR_OFF 41728
#define RED_OFF 41856         // [16][132]
#define ATTN_FLOATS (RED_OFF + 16 * 132)
#define ATTN_SMEM (ATTN_FLOATS * 4)

__global__ __launch_bounds__(256, 1) void attn_kernel()
{
    extern __shared__ float sm[];
    float* Qs = sm + QS_OFF;
    float* Ks = sm + KS_OFF;
    float* Vs = sm + VS_OFF;
    float* Pt = sm + PT_OFF;
    float* mrow = sm + MR_OFF;
    float* lrow = sm + LR_OFF;
    float* arow = sm + AR_OFF;
    float* red  = sm + RED_OFF;

    const int qt = gridDim.x - 1 - blockIdx.x;   // long diagonals launch first
    const int bh = blockIdx.y;
    const int b = bh >> 4, h = bh & 15;
    const int tid = threadIdx.x;
    const int q0 = qt * 128;
    const int bS = b * Ss;
    const size_t hoff = (size_t)h * HDd;

    // ---- load Q tile (natural layout, swizzled, pre-scaled by 1/8) ----
#pragma unroll
    for (int it = 0; it < 8; it++) {
        int idx = it * 1024 + tid * 4;
        int qi = idx >> 6, d = idx & 63;
        float4 v = *(const float4*)&g_q[(size_t)(bS + q0 + qi) * Hh + hoff + d];
        v.x *= 0.125f; v.y *= 0.125f; v.z *= 0.125f; v.w *= 0.125f;
        *(float4*)&Qs[ASW(qi, d >> 2)] = v;
    }
    if (tid < 128) { mrow[tid] = -1e30f; lrow[tid] = 0.f; }

    float acc[8][4];
#pragma unroll
    for (int a = 0; a < 8; a++)
#pragma unroll
        for (int c = 0; c < 4; c++) acc[a][c] = 0.f;

    const int tq = tid & 15, tk = tid >> 4;
    const int tq8 = tq * 8, tk8 = tk * 8;
    const int tyq = tk;          // PV: q group (8 rows)
    const int txd = tq;          // PV: d4 group (4 cols)

    for (int kt = 0; kt <= qt; kt++) {
        __syncthreads();   // prev tile fully consumed
        const int k0g = kt * 128;
#pragma unroll
        for (int it = 0; it < 8; it++) {
            int idx = it * 1024 + tid * 4;
            int ki = idx >> 6, d = idx & 63;
            size_t gidx = (size_t)(bS + k0g + ki) * Hh + hoff + d;
            *(float4*)&Ks[ASW(ki, d >> 2)] = *(const float4*)&g_k[gidx];
            *(float4*)&Vs[ASW(ki, d >> 2)] = *(const float4*)&g_v[gidx];
        }
        __syncthreads();

        // ---- scores: sc[a][c] = K[tk8+a] . Q[tq8+c] ----
        float sc[8][8];
#pragma unroll
        for (int a = 0; a < 8; a++)
#pragma unroll
            for (int c = 0; c < 8; c++) sc[a][c] = 0.f;

#pragma unroll 4
        for (int d4 = 0; d4 < 16; d4++) {
            float4 qa[8];
#pragma unroll
            for (int c = 0; c < 8; c++)
                qa[c] = *(const float4*)&Qs[ASW(tq8 + c, d4)];
#pragma unroll
            for (int a = 0; a < 8; a++) {
                float4 ka = *(const float4*)&Ks[ASW(tk8 + a, d4)];
#pragma unroll
                for (int c = 0; c < 8; c++) {
                    sc[a][c] += ka.x * qa[c].x;
                    sc[a][c] += ka.y * qa[c].y;
                    sc[a][c] += ka.z * qa[c].z;
                    sc[a][c] += ka.w * qa[c].w;
                }
            }
        }

        if (kt == qt) {   // diagonal: causal mask
#pragma unroll
            for (int a = 0; a < 8; a++)
#pragma unroll
                for (int c = 0; c < 8; c++)
                    if (k0g + tk8 + a > q0 + tq8 + c) sc[a][c] = -1e30f;
        }

        // ---- partial max over this thread's 8 k, per q ----
        {
            float pm[8];
#pragma unroll
            for (int c = 0; c < 8; c++) {
                float m = sc[0][c];
#pragma unroll
                for (int a = 1; a < 8; a++) m = fmaxf(m, sc[a][c]);
                pm[c] = m;
            }
            *(float4*)&red[tk * 132 + tq8]     = make_float4(pm[0], pm[1], pm[2], pm[3]);
            *(float4*)&red[tk * 132 + tq8 + 4] = make_float4(pm[4], pm[5], pm[6], pm[7]);
        }
        __syncthreads();
        if (tid < 128) {
            float mn = red[tid];
#pragma unroll
            for (int r2 = 1; r2 < 16; r2++) mn = fmaxf(mn, red[r2 * 132 + tid]);
            float mo = mrow[tid];
            float mx = fmaxf(mn, mo);
            float al = __expf(mo - mx);
            mrow[tid] = mx; arow[tid] = al; lrow[tid] *= al;
        }
        __syncthreads();

        // ---- exp, store P (swizzled), partial sums ----
        {
            float mq[8];
            float4 m0 = *(const float4*)&mrow[tq8];
            float4 m1 = *(const float4*)&mrow[tq8 + 4];
            mq[0] = m0.x; mq[1] = m0.y; mq[2] = m0.z; mq[3] = m0.w;
            mq[4] = m1.x; mq[5] = m1.y; mq[6] = m1.z; mq[7] = m1.w;
            float ps[8];
#pragma unroll
            for (int c = 0; c < 8; c++) ps[c] = 0.f;
#pragma unroll
            for (int a = 0; a < 8; a++) {
                const int row = tk8 + a;
                const int g = PG(row);
                float e[8];
#pragma unroll
                for (int c = 0; c < 8; c++) {
                    e[c] = __expf(sc[a][c] - mq[c]);
                    ps[c] += e[c];
                }
                *(float4*)&Pt[row * 132 + (((tq * 2) ^ g) << 2)] =
                    make_float4(e[0], e[1], e[2], e[3]);
                *(float4*)&Pt[row * 132 + (((tq * 2 + 1) ^ g) << 2)] =
                    make_float4(e[4], e[5], e[6], e[7]);
            }
            *(float4*)&red[tk * 132 + tq8]     = make_float4(ps[0], ps[1], ps[2], ps[3]);
            *(float4*)&red[tk * 132 + tq8 + 4] = make_float4(ps[4], ps[5], ps[6], ps[7]);
        }
        __syncthreads();
        if (tid < 128) {
            float s = red[tid];
#pragma unroll
            for (int r2 = 1; r2 < 16; r2++) s += red[r2 * 132 + tid];
            lrow[tid] += s;
        }

        // ---- PV accumulate (reads arow/Pt/Vs; safe until next loop-top sync)
        {
            float al[8];
            float4 a0 = *(const float4*)&arow[tyq * 8];
            float4 a1 = *(const float4*)&arow[tyq * 8 + 4];
            al[0] = a0.x; al[1] = a0.y; al[2] = a0.z; al[3] = a0.w;
            al[4] = a1.x; al[5] = a1.y; al[6] = a1.z; al[7] = a1.w;
#pragma unroll
            for (int a = 0; a < 8; a++)
#pragma unroll
                for (int c = 0; c < 4; c++) acc[a][c] *= al[a];
#pragma unroll 4
            for (int k = 0; k < 128; k++) {
                const int gk = PG(k);
                float4 p0 = *(const float4*)&Pt[k * 132 + (((tyq * 2) ^ gk) << 2)];
                float4 p1 = *(const float4*)&Pt[k * 132 + (((tyq * 2 + 1) ^ gk) << 2)];
                float4 v  = *(const float4*)&Vs[ASW(k, txd)];
                acc[0][0] += p0.x * v.x; acc[0][1] += p0.x * v.y;
                acc[0][2] += p0.x * v.z; acc[0][3] += p0.x * v.w;
                acc[1][0] += p0.y * v.x; acc[1][1] += p0.y * v.y;
                acc[1][2] += p0.y * v.z; acc[1][3] += p0.y * v.w;
                acc[2][0] += p0.z * v.x; acc[2][1] += p0.z * v.y;
                acc[2][2] += p0.z * v.z; acc[2][3] += p0.z * v.w;
                acc[3][0] += p0.w * v.x; acc[3][1] += p0.w * v.y;
                acc[3][2] += p0.w * v.z; acc[3][3] += p0.w * v.w;
                acc[4][0] += p1.x * v.x; acc[4][1] += p1.x * v.y;
                acc[4][2] += p1.x * v.z; acc[4][3] += p1.x * v.w;
                acc[5][0] += p1.y * v.x; acc[5][1] += p1.y * v.y;
                acc[5][2] += p1.y * v.z; acc[5][3] += p1.y * v.w;
                acc[6][0] += p1.z * v.x; acc[6][1] += p1.z * v.y;
                acc[6][2] += p1.z * v.z; acc[6][3] += p1.z * v.w;
                acc[7][0] += p1.w * v.x; acc[7][1] += p1.w * v.y;
                acc[7][2] += p1.w * v.z; acc[7][3] += p1.w * v.w;
            }
        }
    }
    __syncthreads();

    // ---- normalize + write out [b, s, h, d] ----
    {
        float il[8];
        float4 l0 = *(const float4*)&lrow[tyq * 8];
        float4 l1 = *(const float4*)&lrow[tyq * 8 + 4];
        il[0] = 1.f / l0.x; il[1] = 1.f / l0.y; il[2] = 1.f / l0.z; il[3] = 1.f / l0.w;
        il[4] = 1.f / l1.x; il[5] = 1.f / l1.y; il[6] = 1.f / l1.z; il[7] = 1.f / l1.w;
#pragma unroll
        for (int a = 0; a < 8; a++) {
            int gq = q0 + tyq * 8 + a;
            float4 o = make_float4(acc[a][0] * il[a], acc[a][1] * il[a],
                                   acc[a][2] * il[a], acc[a][3] * il[a]);
            *(float4*)&g_o[(size_t)(bS + gq) * Hh + hoff + txd * 4] = o;
        }
    }
}

// ---------------------------------------------------------------------------

extern "C" void kernel_launch(void* const* d_in, const int* in_sizes, int n_in,
                              void* d_out, int out_size)
{
    const float* X   = (const float*)d_in[0];
    const float* fc  = (const float*)d_in[1];
    const float* fs  = (const float*)d_in[2];
    const int*   pos = (const int*)d_in[3];
    const float* Wq  = (const float*)d_in[4];
    const float* Wk  = (const float*)d_in[5];
    const float* Wv  = (const float*)d_in[6];
    const float* Wo  = (const float*)d_in[7];
    float* out = (float*)d_out;

    float *pq, *pk, *pv, *po;
    cudaGetSymbolAddress((void**)&pq, g_q);
    cudaGetSymbolAddress((void**)&pk, g_k);
    cudaGetSymbolAddress((void**)&pv, g_v);
    cudaGetSymbolAddress((void**)&po, g_o);

    cudaFuncSetAttribute(gemm_tc,
                         cudaFuncAttributeMaxDynamicSharedMemorySize, GEMM_DSMEM);
    cudaFuncSetAttribute(attn_kernel,
                         cudaFuncAttributeMaxDynamicSharedMemorySize, ATTN_SMEM);

    // 1) QKV projections (tensor cores)
    gemm_tc<<<dim3(Mm / 128, Hh / 128, 3), 256, GEMM_DSMEM>>>(
        X, Wq, Wk, Wv, pq, pk, pv);

    // 2) RoPE
    {
        int total = Mm * (Hh / 2);
        rope_kernel<<<(total + 255) / 256, 256>>>(fc, fs, pos);
    }

    // 3) Causal attention (fp32, 128x128 tiles)
    attn_kernel<<<dim3(Ss / 128, Bb * NHh), 256, ATTN_SMEM>>>();

    // 4) Output projection (tensor cores)
    gemm_tc<<<dim3(Mm / 128, Hh / 128, 1), 256, GEMM_DSMEM>>>(
        po, Wo, Wo, Wo, out, out, out);
}